// round 1
// baseline (speedup 1.0000x reference)
#include <cuda_runtime.h>
#include <math.h>
#include <float.h>

#define D_TOT 496
#define F_TOT 40
#define T_STEPS 1000
#define B_MAX 32768

// ---------------- device scratch (no allocations allowed) ----------------
__device__ float g_log_alpha[T_STEPS];
__device__ float g_log_1m_alpha[T_STEPS];
__device__ float g_log_ca[T_STEPS];
__device__ float g_log_1m_ca[T_STEPS];
__device__ float g_cspart[16 * D_TOT];
__device__ float g_colsum[D_TOT];
__device__ float g_rowloss[B_MAX];

// ---------------- helpers ----------------
__device__ __forceinline__ float lae(float a, float b) {
    // logaddexp, stable
    float m = fmaxf(a, b);
    float n = fminf(a, b);
    return m + log1pf(expf(n - m));
}

// Segmented butterfly reductions. Segments are power-of-2 sized AND aligned
// within the warp; `width` is the per-lane segment width (0 for pad lanes).
__device__ __forceinline__ float bflyMax(float v, int width) {
#pragma unroll
    for (int d = 1; d < 32; d <<= 1) {
        float o = __shfl_xor_sync(0xFFFFFFFFu, v, d);
        if (width > d) v = fmaxf(v, o);
    }
    return v;
}
__device__ __forceinline__ float bflySum(float v, int width) {
#pragma unroll
    for (int d = 1; d < 32; d <<= 1) {
        float o = __shfl_xor_sync(0xFFFFFFFFu, v, d);
        if (width > d) v += o;
    }
    return v;
}
// argmax with first-max (min index) tie break — matches reference semantics
__device__ __forceinline__ void bflyArgmax(float& v, int& i, int width) {
#pragma unroll
    for (int d = 1; d < 32; d <<= 1) {
        float ov = __shfl_xor_sync(0xFFFFFFFFu, v, d);
        int   oi = __shfl_xor_sync(0xFFFFFFFFu, i, d);
        if (width > d) {
            if (ov > v || (ov == v && oi < i)) { v = ov; i = oi; }
        }
    }
}

// ---------------- prologue: diffusion tables + W column sums ----------------
__global__ void k_prep(const float* __restrict__ W) {
    int tid = threadIdx.x;
    if (blockIdx.x == 0) {
        // Beta schedule in double to match numpy float64 cumprod, then cast.
        __shared__ double sd[1024];
        double lad = 0.0;
        if (tid < T_STEPS) {
            double beta = 1e-4 + (double)tid * ((0.02 - 1e-4) / 999.0);
            double alpha = 1.0 - beta;
            lad = log(alpha);
            g_log_alpha[tid] = (float)lad;
            g_log_1m_alpha[tid] = (float)log(beta);   // 1 - alpha == beta exactly
        }
        sd[tid] = lad;
        __syncthreads();
        // Hillis-Steele inclusive scan (double)
        for (int off = 1; off < 1024; off <<= 1) {
            double add = (tid >= off) ? sd[tid - off] : 0.0;
            __syncthreads();
            sd[tid] += add;
            __syncthreads();
        }
        if (tid < T_STEPS) {
            double cum = sd[tid];                      // log(cumprod(alpha))
            g_log_ca[tid] = (float)cum;
            g_log_1m_ca[tid] = (float)log(-expm1(cum)); // log(1 - ca), no cancellation
        }
    } else {
        // colsum partials: block p sums 31 rows of W (16*31 = 496)
        int p = blockIdx.x - 1;
        int r0 = p * 31;
        if (tid < D_TOT) {
            float acc = 0.f;
#pragma unroll
            for (int r = 0; r < 31; r++)
                acc += W[(r0 + r) * D_TOT + tid];
            g_cspart[p * D_TOT + tid] = acc;
        }
    }
}

__global__ void k_csfin() {
    int j = threadIdx.x;
    if (j < D_TOT) {
        float s = 0.f;
#pragma unroll
        for (int p = 0; p < 16; p++) s += g_cspart[p * D_TOT + j];
        g_colsum[j] = s;
    }
}

// ---------------- main: one CTA per batch row ----------------
// Warp g owns feature group g (5 features, 62 columns: 2+4+8+16+32).
// Slot A per lane: features of size 2/4/8/16 packed into p2-aligned lane
// ranges [0,2),[4,8),[8,16),[16,32) (lanes 2-3 are pads).
// Slot B per lane: the 32-wide feature (cols 30..61 of the group).
__global__ void __launch_bounds__(256) k_main(
    const int* __restrict__ x0, const int* __restrict__ ts,
    const float* __restrict__ uni, const float* __restrict__ W,
    const float* __restrict__ bias, const float* __restrict__ temb)
{
    const int row = blockIdx.x;
    const int tid = threadIdx.x;
    const int lane = tid & 31;
    const int g = tid >> 5;

    __shared__ int   sX0[F_TOT];
    __shared__ int   sWin[F_TOT];
    __shared__ float sRed[3][8];

    if (tid < F_TOT) sX0[tid] = x0[row * F_TOT + tid];
    const int t = ts[row];
    __syncthreads();

    // static per-lane layout
    int la, base, width, idxin;
    if (lane < 2)       { la = 0; base = 0;  width = 2;  idxin = lane; }
    else if (lane < 4)  { la = 0; base = 0;  width = 0;  idxin = 0;    }   // pad
    else if (lane < 8)  { la = 1; base = 2;  width = 4;  idxin = lane - 4; }
    else if (lane < 16) { la = 2; base = 6;  width = 8;  idxin = lane - 8; }
    else                { la = 3; base = 14; width = 16; idxin = lane - 16; }
    const bool validA = (width != 0);
    const int gbase = g * 62;
    const int colA = gbase + base + idxin;
    const int featA = g * 5 + la;
    const float lncA = logf(validA ? (float)width : 2.0f);  // nc == width
    const int colB = gbase + 30 + lane;
    const int featB = g * 5 + 4;
    const float lncB = logf(32.0f);

    // per-timestep scalars
    const int tm1 = (t > 0) ? (t - 1) : 0;
    const float lc   = g_log_ca[t];
    const float l1c  = g_log_1m_ca[t];
    const float laa  = g_log_alpha[t];
    const float l1a  = g_log_1m_alpha[t];
    const float lcm  = g_log_ca[tm1];
    const float l1cm = g_log_1m_ca[tm1];
    const float lcT  = g_log_ca[T_STEPS - 1];
    const float l1cT = g_log_1m_ca[T_STEPS - 1];

    const float LOGEPS = -69.07755279f;   // log(1e-30f)

    // log one-hot of x0
    const int c0A = gbase + base + sX0[featA];
    const int c0B = gbase + 30 + sX0[featB];
    const float lx0A = (validA && colA == c0A) ? 0.f : LOGEPS;
    const float lx0B = (colB == c0B) ? 0.f : LOGEPS;

    // q_prior(log_x0, t)
    const float qpA = lae(lx0A + lc, l1c - lncA);
    const float qpB = lae(lx0B + lc, l1c - lncB);

    // Gumbel-max categorical sample per feature
    const float uA = uni[row * D_TOT + colA];
    const float uB = uni[row * D_TOT + colB];
    const float gumA = -logf(-logf(uA + 1e-30f) + 1e-30f);
    const float gumB = -logf(-logf(uB + 1e-30f) + 1e-30f);

    float zA = validA ? (gumA + qpA) : -FLT_MAX;
    float zB = gumB + qpB;
    int iA = validA ? colA : 0x7FFFFFFF;
    int iB = colB;
    bflyArgmax(zA, iA, width);
    bflyArgmax(zB, iB, 32);

    if (validA && idxin == 0) sWin[featA] = iA * D_TOT;   // premultiplied row offset
    if (lane == 0)            sWin[featB] = iB * D_TOT;
    __syncthreads();

    const float lxtA = (colA == iA) ? 0.f : LOGEPS;
    const float lxtB = (colB == iB) ? 0.f : LOGEPS;

    // ---- W gather: pred[j] = L*(colsum[j] - sum_f W[win_f, j]) + b + t_emb ----
    float gsA = 0.f, gsB = 0.f;
#pragma unroll
    for (int f0 = 0; f0 < F_TOT; f0 += 8) {
        int id[8];
#pragma unroll
        for (int k = 0; k < 8; k++) id[k] = sWin[f0 + k];
#pragma unroll
        for (int k = 0; k < 8; k++) {
            gsA += W[id[k] + colA];
            gsB += W[id[k] + colB];
        }
    }

    const float predA = LOGEPS * (g_colsum[colA] - gsA) + bias[colA] + temb[t * D_TOT + colA];
    const float predB = LOGEPS * (g_colsum[colB] - gsB) + bias[colB] + temb[t * D_TOT + colB];

    // per-segment log_softmax of pred -> log_x0_hat
    float mpA = bflyMax(validA ? predA : -FLT_MAX, width);
    float epA = validA ? expf(predA - mpA) : 0.f;
    float lseA = mpA + logf(bflySum(epA, width));
    float mpB = bflyMax(predB, 32);
    float lseB = mpB + logf(bflySum(expf(predB - mpB), 32));
    const float lh0A = predA - lseA;
    const float lh0B = predB - lseB;

    // q_one_timestep(log_xt, t) — shared by both posteriors
    const float qoA = lae(lxtA + laa, l1a - lncA);
    const float qoB = lae(lxtB + laa, l1a - lncB);

    const bool t0 = (t == 0);
    const float evA = t0 ? lx0A : lae(lx0A + lcm, l1cm - lncA);
    const float evB = t0 ? lx0B : lae(lx0B + lcm, l1cm - lncB);
    const float unA = evA + qoA, unB = evB + qoB;

    const float ev2A = t0 ? lh0A : lae(lh0A + lcm, l1cm - lncA);
    const float ev2B = t0 ? lh0B : lae(lh0B + lcm, l1cm - lncB);
    const float un2A = ev2A + qoA, un2B = ev2B + qoB;

    // normalize both posteriors per segment
    float m1A = bflyMax(validA ? unA : -FLT_MAX, width);
    float l1A = m1A + logf(bflySum(validA ? expf(unA - m1A) : 0.f, width));
    float m1B = bflyMax(unB, 32);
    float l1B = m1B + logf(bflySum(expf(unB - m1B), 32));
    const float ltA = unA - l1A, ltB = unB - l1B;

    float m2A = bflyMax(validA ? un2A : -FLT_MAX, width);
    float l2A = m2A + logf(bflySum(validA ? expf(un2A - m2A) : 0.f, width));
    float m2B = bflyMax(un2B, 32);
    float l2B = m2B + logf(bflySum(expf(un2B - m2B), 32));
    const float leA = un2A - l2A, leB = un2B - l2B;

    const float klA = expf(ltA) * (ltA - leA);
    const float klB = expf(ltB) * (ltB - leB);
    const float deA = -((colA == c0A) ? 1.f : 1e-30f) * leA;
    const float deB = -((colB == c0B) ? 1.f : 1e-30f) * leB;

    // kl_prior vs uniform
    const float lqA = lae(lx0A + lcT, l1cT - lncA);
    const float lqB = lae(lx0B + lcT, l1cT - lncB);
    const float prA = expf(lqA) * (lqA + lncA);
    const float prB = expf(lqB) * (lqB + lncB);

    float sk = (validA ? klA : 0.f) + klB;
    float sde = (validA ? deA : 0.f) + deB;
    float sp = (validA ? prA : 0.f) + prB;
    sk = bflySum(sk, 32);
    sde = bflySum(sde, 32);
    sp = bflySum(sp, 32);
    if (lane == 0) { sRed[0][g] = sk; sRed[1][g] = sde; sRed[2][g] = sp; }
    __syncthreads();
    if (tid == 0) {
        float K = 0.f, Dn = 0.f, P = 0.f;
#pragma unroll
        for (int i = 0; i < 8; i++) { K += sRed[0][i]; Dn += sRed[1][i]; P += sRed[2][i]; }
        const float diff = t0 ? Dn : K;
        g_rowloss[row] = diff * 1000.0f + P;
    }
}

// ---------------- deterministic final mean ----------------
__global__ void k_reduce(float* __restrict__ out, int B) {
    __shared__ float s[1024];
    int tid = threadIdx.x;
    float a = 0.f;
    for (int i = tid; i < B; i += 1024) a += g_rowloss[i];
    s[tid] = a;
    __syncthreads();
    for (int off = 512; off > 0; off >>= 1) {
        if (tid < off) s[tid] += s[tid + off];
        __syncthreads();
    }
    if (tid == 0) out[0] = s[0] / (float)B;
}

// ---------------- launch ----------------
extern "C" void kernel_launch(void* const* d_in, const int* in_sizes, int n_in,
                              void* d_out, int out_size) {
    const int*   x0   = (const int*)d_in[0];
    const int*   ts   = (const int*)d_in[1];
    const float* uni  = (const float*)d_in[2];
    const float* W    = (const float*)d_in[3];
    const float* bias = (const float*)d_in[4];
    const float* temb = (const float*)d_in[5];
    float* out = (float*)d_out;
    const int B = in_sizes[1];   // timesteps count == batch

    k_prep<<<17, 1024>>>(W);
    k_csfin<<<1, 512>>>();
    k_main<<<B, 256>>>(x0, ts, uni, W, bias, temb);
    k_reduce<<<1, 1024>>>(out, B);
}